// round 8
// baseline (speedup 1.0000x reference)
#include <cuda_runtime.h>
#include <cuda_fp16.h>
#include <math.h>

#define DNODE 64
#define NMAX  100000
#define EMAX  1200000
#define EPSN  1e-15f
#define ACLIP (1.0f - 1e-7f)
#define SCAN_BLK 4096

// ---------------- scratch (no allocation allowed) ----------------
__device__ __half g_h[(size_t)NMAX * DNODE];   // linear-layer output (fp16)
__device__ float  g_buf[(size_t)NMAX * DNODE]; // pull accumulator (fp32)
__device__ int    g_csr[EMAX];                 // src ids grouped by dst
__device__ int    g_rs[NMAX + 1];              // CSR offsets by dst
__device__ int    g_deg[NMAX];
__device__ int    g_cur[NMAX];
__device__ int    g_incl[NMAX];
__device__ int    g_part[1024];
__device__ float  g_inv[NMAX];

// ============ CSR build ============
__global__ void zero_int_k(int* a, int n) {
    int i = blockIdx.x * blockDim.x + threadIdx.x;
    if (i < n) a[i] = 0;
}

__global__ void count_k(const int* __restrict__ dst, int* __restrict__ deg, int E) {
    int i = blockIdx.x * blockDim.x + threadIdx.x;
    if (i < E) atomicAdd(&deg[dst[i]], 1);
}

// per-block inclusive scan (4096 elems/block) + block partial sums
__global__ __launch_bounds__(256) void scan1_k(const int* __restrict__ deg,
                                               int* __restrict__ incl,
                                               int* __restrict__ part, int n) {
    __shared__ int sh[256];
    int tid = threadIdx.x;
    int base = blockIdx.x * SCAN_BLK + tid * 16;
    int v[16];
    int s = 0;
    #pragma unroll
    for (int i = 0; i < 16; i++) {
        int idx = base + i;
        v[i] = (idx < n) ? deg[idx] : 0;
        s += v[i];
    }
    sh[tid] = s;
    __syncthreads();
    for (int off = 1; off < 256; off <<= 1) {
        int t = (tid >= off) ? sh[tid - off] : 0;
        __syncthreads();
        sh[tid] += t;
        __syncthreads();
    }
    int run = sh[tid] - s;  // exclusive prefix of this thread within block
    #pragma unroll
    for (int i = 0; i < 16; i++) {
        run += v[i];
        int idx = base + i;
        if (idx < n) incl[idx] = run;
    }
    if (tid == 255) part[blockIdx.x] = sh[255];
}

// parallel warp scan over block partials (handles any nb via carry loop)
__global__ void scan2_k(int* part, int nb) {
    int lane = threadIdx.x;  // 32 threads
    int carry = 0;
    for (int base = 0; base < nb; base += 32) {
        int idx = base + lane;
        int v = (idx < nb) ? part[idx] : 0;
        int x = v;
        #pragma unroll
        for (int off = 1; off < 32; off <<= 1) {
            int t = __shfl_up_sync(0xffffffffu, x, off);
            if (lane >= off) x += t;
        }
        if (idx < nb) part[idx] = carry + x - v;  // exclusive
        carry += __shfl_sync(0xffffffffu, x, 31);
    }
}

__global__ void finalize_k(const int* __restrict__ incl, const int* __restrict__ deg,
                           const int* __restrict__ part, int* __restrict__ rs,
                           int* __restrict__ cur, float* __restrict__ inv,
                           int n, int E) {
    int i = blockIdx.x * blockDim.x + threadIdx.x;
    if (i < n) {
        int d = deg[i];
        rs[i] = incl[i] - d + part[i / SCAN_BLK];  // exclusive scan
        cur[i] = 0;
        inv[i] = (d > 0) ? (1.0f / (float)d) : 0.0f;
    }
    if (i == 0) rs[n] = E;
}

__global__ void fill_k(const int* __restrict__ src, const int* __restrict__ dst,
                       const int* __restrict__ rs, int* __restrict__ cur,
                       int* __restrict__ csr, int E) {
    int e = blockIdx.x * blockDim.x + threadIdx.x;
    if (e < E) {
        int d = dst[e];
        int p = atomicAdd(&cur[d], 1);
        csr[rs[d] + p] = src[e];
    }
}

// ============ GEMM: h = (scale(row) * X) @ W^T + b  (fp16 output) ============
// LOGMAP=1: scale = atanh-factor from row norm. LOGMAP=0: scale = invd[row].
#define PITCH 68
template <int LOGMAP>
__global__ __launch_bounds__(256) void gemm_k(
    const float* __restrict__ X, const float* __restrict__ W,
    const float* __restrict__ bias, const float* __restrict__ curv,
    const float* __restrict__ invd, __half* __restrict__ out, int n)
{
    __shared__ float Xs[DNODE * PITCH];
    __shared__ float Ws[DNODE * PITCH];
    __shared__ float fac[DNODE];
    __shared__ float bsh[DNODE];

    int tid = threadIdx.x;
    int rowbase = blockIdx.x * DNODE;

    for (int i = tid * 4; i < DNODE * DNODE; i += 1024) {
        int r = i >> 6, c = i & 63;
        float4 w = *(const float4*)(W + i);
        *(float4*)&Ws[r * PITCH + c] = w;
        int gr = rowbase + r;
        float4 xv = (gr < n) ? *(const float4*)(X + (size_t)gr * DNODE + c)
                             : make_float4(0.f, 0.f, 0.f, 0.f);
        *(float4*)&Xs[r * PITCH + c] = xv;
    }
    if (tid < DNODE) bsh[tid] = bias[tid];
    __syncthreads();

    if (LOGMAP) {
        int r = tid >> 2, q = tid & 3;
        float s = 0.f;
        #pragma unroll
        for (int c = 0; c < 16; c++) {
            float v = Xs[r * PITCH + q * 16 + c];
            s += v * v;
        }
        s += __shfl_down_sync(0xffffffffu, s, 2, 4);
        s += __shfl_down_sync(0xffffffffu, s, 1, 4);
        if (q == 0) {
            float sc = sqrtf(fabsf(curv[0]));
            float norm = fmaxf(sqrtf(s), EPSN);
            float arg = fminf(sc * norm, ACLIP);
            fac[r] = atanhf(arg) / (sc * norm);
        }
    } else {
        if (tid < DNODE) {
            int gr = rowbase + tid;
            fac[tid] = (gr < n) ? invd[gr] : 0.f;
        }
    }
    __syncthreads();

    for (int i = tid; i < DNODE * DNODE; i += 256) {
        int r = i >> 6;
        Xs[r * PITCH + (i & 63)] *= fac[r];
    }
    __syncthreads();

    int r4 = tid >> 4;   // rows r4*4+i
    int c4 = tid & 15;   // cols c4+16*j
    float acc[4][4] = {};
    #pragma unroll
    for (int k = 0; k < DNODE; k += 4) {
        float4 tv[4], wv[4];
        #pragma unroll
        for (int i = 0; i < 4; i++)
            tv[i] = *(float4*)&Xs[(r4 * 4 + i) * PITCH + k];
        #pragma unroll
        for (int j = 0; j < 4; j++)
            wv[j] = *(float4*)&Ws[(c4 + 16 * j) * PITCH + k];
        #pragma unroll
        for (int i = 0; i < 4; i++)
            #pragma unroll
            for (int j = 0; j < 4; j++) {
                acc[i][j] = fmaf(tv[i].x, wv[j].x, acc[i][j]);
                acc[i][j] = fmaf(tv[i].y, wv[j].y, acc[i][j]);
                acc[i][j] = fmaf(tv[i].z, wv[j].z, acc[i][j]);
                acc[i][j] = fmaf(tv[i].w, wv[j].w, acc[i][j]);
            }
    }
    #pragma unroll
    for (int i = 0; i < 4; i++) {
        int row = rowbase + r4 * 4 + i;
        if (row < n) {
            #pragma unroll
            for (int j = 0; j < 4; j++) {
                int col = c4 + 16 * j;
                out[(size_t)row * DNODE + col] = __float2half(acc[i][j] + bsh[col]);
            }
        }
    }
}

// ============ pull: acc[d] = sum_{e in CSR(d)} h[csr[e]]  (fp16 gather, fp32 acc)
// FINAL=0: write fp32 acc to buf. FINAL=1: apply invdeg + expmap0, write to out.
template <int FINAL>
__global__ __launch_bounds__(256) void pull_k(
    const __half* __restrict__ h, const int* __restrict__ rs,
    const int* __restrict__ csr, const float* __restrict__ invd,
    const float* __restrict__ curv, float* __restrict__ outp, int n)
{
    int gw = (blockIdx.x * 256 + threadIdx.x) >> 5;
    int lane = threadIdx.x & 31;
    if (gw >= n) return;
    int beg = rs[gw], end = rs[gw + 1];
    const __half2* hp = (const __half2*)h;
    float ax = 0.f, ay = 0.f;
    int i = beg;
    for (; i + 3 < end; i += 4) {
        int s0 = csr[i], s1 = csr[i + 1], s2 = csr[i + 2], s3 = csr[i + 3];
        float2 v0 = __half22float2(hp[(size_t)s0 * 32 + lane]);
        float2 v1 = __half22float2(hp[(size_t)s1 * 32 + lane]);
        float2 v2 = __half22float2(hp[(size_t)s2 * 32 + lane]);
        float2 v3 = __half22float2(hp[(size_t)s3 * 32 + lane]);
        ax += (v0.x + v1.x) + (v2.x + v3.x);
        ay += (v0.y + v1.y) + (v2.y + v3.y);
    }
    for (; i < end; i++) {
        int s0 = csr[i];
        float2 v0 = __half22float2(hp[(size_t)s0 * 32 + lane]);
        ax += v0.x;
        ay += v0.y;
    }
    if (FINAL) {
        float w = invd[gw];
        float ua = ax * w, ub = ay * w;
        float ss = ua * ua + ub * ub;
        #pragma unroll
        for (int o = 16; o; o >>= 1) ss += __shfl_xor_sync(0xffffffffu, ss, o);
        float sc = sqrtf(fabsf(curv[0]));
        float norm = fmaxf(sqrtf(ss), EPSN);
        float f = tanhf(sc * norm) / (sc * norm);
        ((float2*)outp)[(size_t)gw * 32 + lane] = make_float2(f * ua, f * ub);
    } else {
        ((float2*)outp)[(size_t)gw * 32 + lane] = make_float2(ax, ay);
    }
}

// ---------------- launch ----------------
extern "C" void kernel_launch(void* const* d_in, const int* in_sizes, int n_in,
                              void* d_out, int out_size)
{
    const int*   src  = (const int*)d_in[0];
    const int*   dst  = (const int*)d_in[1];
    const float* emb  = (const float*)d_in[2];
    const float* W1   = (const float*)d_in[3];
    const float* b1   = (const float*)d_in[4];
    const float* W2   = (const float*)d_in[5];
    const float* b2   = (const float*)d_in[6];
    const float* curv = (const float*)d_in[7];
    float* out = (float*)d_out;

    const int E = in_sizes[0];
    const int N = in_sizes[2] / DNODE;

    __half* h;
    float *buf, *inv;
    int *csr, *rs, *deg, *cur, *incl, *part;
    cudaGetSymbolAddress((void**)&h,    g_h);
    cudaGetSymbolAddress((void**)&buf,  g_buf);
    cudaGetSymbolAddress((void**)&inv,  g_inv);
    cudaGetSymbolAddress((void**)&csr,  g_csr);
    cudaGetSymbolAddress((void**)&rs,   g_rs);
    cudaGetSymbolAddress((void**)&deg,  g_deg);
    cudaGetSymbolAddress((void**)&cur,  g_cur);
    cudaGetSymbolAddress((void**)&incl, g_incl);
    cudaGetSymbolAddress((void**)&part, g_part);

    const int TB = 256;
    int nb_scan = (N + SCAN_BLK - 1) / SCAN_BLK;

    // ---- CSR build (by dst) ----
    zero_int_k<<<(N + TB - 1) / TB, TB>>>(deg, N);
    count_k<<<(E + TB - 1) / TB, TB>>>(dst, deg, E);
    scan1_k<<<nb_scan, TB>>>(deg, incl, part, N);
    scan2_k<<<1, 32>>>(part, nb_scan);
    finalize_k<<<(N + TB - 1) / TB, TB>>>(incl, deg, part, rs, cur, inv, N, E);
    fill_k<<<(E + TB - 1) / TB, TB>>>(src, dst, rs, cur, csr, E);

    int gemm_blocks = (N + DNODE - 1) / DNODE;
    int pull_blocks = (N * 32 + TB - 1) / TB;

    // ---- layer 1: h1 = logmap0(emb) @ W1^T + b1 ; u1 = pull-sum ----
    gemm_k<1><<<gemm_blocks, TB>>>(emb, W1, b1, curv, inv, h, N);
    pull_k<0><<<pull_blocks, TB>>>(h, rs, csr, inv, curv, buf, N);

    // ---- layer 2: logmap0(expmap0(u)) == u, so t2 = u1*inv_deg directly ----
    gemm_k<0><<<gemm_blocks, TB>>>(buf, W2, b2, curv, inv, h, N);

    // ---- final pull fused with expmap0(u2 * inv_deg) -> d_out ----
    pull_k<1><<<pull_blocks, TB>>>(h, rs, csr, inv, curv, out, N);
}